// round 2
// baseline (speedup 1.0000x reference)
#include <cuda_runtime.h>
#include <cstdint>

#define N_PTS   400000
#define NXY     468
#define CANVAS  (468 * 468)          // 219024
#define VXY     0.32f
#define VZf     6.0f
#define PCMINX  (-74.88f)
#define PCMINY  (-74.88f)
#define PCMINZ  (-2.0f)

// -------- scratch (static device globals; no allocations allowed) ----------
__device__ int   g_flat[N_PTS];
__device__ int   g_cnt[CANVAS];
__device__ float g_vsum[CANVAS * 3];
__device__ float g_v1[CANVAS * 64];     // 56 MB

// packed f32x2 FMA (Blackwell FFMA2) — d = a*b + d, lanewise on 2 packed fp32
__device__ __forceinline__ void fma2(uint64_t& d, uint64_t a, uint64_t b) {
    asm("fma.rn.f32x2 %0, %1, %2, %0;" : "+l"(d) : "l"(a), "l"(b));
}

// ---------------------------------------------------------------------------
// K0: zero cnt / vsum / v1 / out
// ---------------------------------------------------------------------------
__global__ void k_init(float* __restrict__ out) {
    int idx = blockIdx.x * blockDim.x + threadIdx.x;
    int stride = gridDim.x * blockDim.x;
    const int n4 = (CANVAS * 64) / 4;
    float4 z = make_float4(0.f, 0.f, 0.f, 0.f);
    float4* o4 = (float4*)out;
    float4* v4 = (float4*)g_v1;
    for (int i = idx; i < n4; i += stride) {
        o4[i] = z;
        v4[i] = z;
    }
    for (int i = idx; i < CANVAS; i += stride) {
        g_cnt[i] = 0;
        g_vsum[3 * i + 0] = 0.f;
        g_vsum[3 * i + 1] = 0.f;
        g_vsum[3 * i + 2] = 0.f;
    }
}

// ---------------------------------------------------------------------------
// K1: per-point voxel index + count / xyz-sum scatter
// ---------------------------------------------------------------------------
__device__ __forceinline__ int voxel_coord(float v, float vmin, float vox, int nmax) {
    int c = (int)floorf(__fdiv_rn(v - vmin, vox));
    return min(max(c, 0), nmax - 1);
}

__global__ void k_scatter(const float* __restrict__ pts) {
    int i = blockIdx.x * blockDim.x + threadIdx.x;
    if (i >= N_PTS) return;
    float x = pts[i * 5 + 0];
    float y = pts[i * 5 + 1];
    float z = pts[i * 5 + 2];
    int cx = voxel_coord(x, PCMINX, VXY, NXY);
    int cy = voxel_coord(y, PCMINY, VXY, NXY);
    int flat = cy * NXY + cx;         // NZ==1 -> cz always 0
    g_flat[i] = flat;
    atomicAdd(&g_cnt[flat], 1);
    atomicAdd(&g_vsum[3 * flat + 0], x);
    atomicAdd(&g_vsum[3 * flat + 1], y);
    atomicAdd(&g_vsum[3 * flat + 2], z);
}

// ---------------------------------------------------------------------------
// shared helper: pf1 for one point; lane produces outputs (lane, lane+32)
// ---------------------------------------------------------------------------
__device__ __forceinline__ void pf1_point(const float* __restrict__ pts,
                                          const float* __restrict__ sW1,
                                          int gp, int lane,
                                          float& o0, float& o1) {
    float x  = pts[gp * 5 + 0];
    float y  = pts[gp * 5 + 1];
    float z  = pts[gp * 5 + 2];
    float p3 = pts[gp * 5 + 3];
    float p4 = pts[gp * 5 + 4];

    int flat = g_flat[gp];
    float inv = 1.0f / fmaxf((float)g_cnt[flat], 1.0f);
    float mx = g_vsum[3 * flat + 0] * inv;
    float my = g_vsum[3 * flat + 1] * inv;
    float mz = g_vsum[3 * flat + 2] * inv;

    int cxv = flat % NXY;
    int cyv = flat / NXY;

    float f[11];
    f[0] = x;  f[1] = y;  f[2] = z;  f[3] = p3;  f[4] = p4;
    f[5] = x - mx;  f[6] = y - my;  f[7] = z - mz;
    f[8]  = x - ((float)cxv * VXY + (VXY * 0.5f + PCMINX));
    f[9]  = y - ((float)cyv * VXY + (VXY * 0.5f + PCMINY));
    f[10] = z - (VZf * 0.5f + PCMINZ);

    float a0 = 0.f, a1 = 0.f;
    #pragma unroll
    for (int k = 0; k < 11; k++) {
        a0 = fmaf(f[k], sW1[k * 64 + lane], a0);
        a1 = fmaf(f[k], sW1[k * 64 + lane + 32], a1);
    }
    o0 = fmaxf(a0, 0.f);
    o1 = fmaxf(a1, 0.f);
}

// ---------------------------------------------------------------------------
// K2: build v1 = segment_max(pf1) via atomicMax (values >= 0, init 0 -> int max ok)
// ---------------------------------------------------------------------------
__global__ void k_pf1(const float* __restrict__ pts, const float* __restrict__ W1) {
    __shared__ float sW1[11 * 64];
    int tid = threadIdx.x;
    for (int i = tid; i < 11 * 64; i += 256) sW1[i] = W1[i];
    __syncthreads();

    int warp = tid >> 5;
    int lane = tid & 31;
    int i = blockIdx.x * 8 + warp;
    if (i >= N_PTS) return;

    float a0, a1;
    pf1_point(pts, sW1, i, lane, a0, a1);

    int flat = g_flat[i];
    if (a0 > 0.f) atomicMax((int*)&g_v1[flat * 64 + lane],      __float_as_int(a0));
    if (a1 > 0.f) atomicMax((int*)&g_v1[flat * 64 + lane + 32], __float_as_int(a1));
}

// ---------------------------------------------------------------------------
// K3: pf2 = relu([pf1, v1[flat]] @ W2), scatter-max into out
// Block: 256 points x 64 outputs, 256 threads, 8x8 micro-tile (4 row-pairs),
// packed f32x2 FMAs. A stored k-major in shared; W2 duplicated {w,w}.
// pf1 recomputed on the fly (no 102MB intermediate).
// ---------------------------------------------------------------------------
#define BP      256
#define SAT_LD  258              // (256 pts + 2 pad), even -> 8B-aligned pairs
#define SAT_WORDS (64 * SAT_LD)  // 16512
#define SWD_WORDS (64 * 128)     // 8192
#define SMEM_WORDS (SAT_WORDS + SWD_WORDS + 11 * 64)
#define SMEM_BYTES (SMEM_WORDS * 4)

__global__ __launch_bounds__(256, 2)
void k_pf2(const float* __restrict__ pts, const float* __restrict__ W1,
           const float* __restrict__ W2, float* __restrict__ out) {
    extern __shared__ float smem[];
    float* sAt = smem;                       // [64][SAT_LD] k-major A tile
    float* sWd = smem + SAT_WORDS;           // [64][128]    duplicated W2 chunk
    float* sW1 = smem + SAT_WORDS + SWD_WORDS;

    int tid  = threadIdx.x;
    int lane = tid & 31;
    int w    = tid >> 5;
    int p0   = blockIdx.x * BP;

    int ty = tid >> 3;   // 0..31: owns rows ty*8 .. ty*8+7
    int cx = tid & 7;    // 0..7 : owns cols cx*8 .. cx*8+7

    for (int i = tid; i < 11 * 64; i += 256) sW1[i] = W1[i];

    uint64_t acc[4][8];
    #pragma unroll
    for (int rp = 0; rp < 4; rp++)
        #pragma unroll
        for (int c = 0; c < 8; c++) acc[rp][c] = 0ull;

    #pragma unroll 1
    for (int chunk = 0; chunk < 2; chunk++) {
        // ---- stage duplicated W2 chunk: sWd[k][2c]=sWd[k][2c+1]=W2[chunk*64+k][c]
        for (int i = tid; i < 4096; i += 256) {
            int k = i >> 6, c = i & 63;
            float wv = W2[(chunk * 64 + k) * 64 + c];
            sWd[k * 128 + 2 * c]     = wv;
            sWd[k * 128 + 2 * c + 1] = wv;
        }
        // ---- stage A tile (k-major): warp w handles points w*32 .. w*32+31
        if (chunk == 0) {
            if (w == 0 && tid < 32) { /* ensure sW1 visible: covered by sync below */ }
            __syncthreads();   // sW1 ready (first iter) / prev mainloop done
            for (int i = 0; i < 32; i++) {
                int p = w * 32 + i;
                int gp = p0 + p;
                float a0 = 0.f, a1 = 0.f;
                if (gp < N_PTS) pf1_point(pts, sW1, gp, lane, a0, a1);
                sAt[lane * SAT_LD + p]        = a0;
                sAt[(lane + 32) * SAT_LD + p] = a1;
            }
        } else {
            __syncthreads();   // prev mainloop done before overwrite
            for (int i = 0; i < 32; i++) {
                int p = w * 32 + i;
                int gp = p0 + p;
                float a0 = 0.f, a1 = 0.f;
                if (gp < N_PTS) {
                    int fl = g_flat[gp];
                    a0 = g_v1[(size_t)fl * 64 + lane];
                    a1 = g_v1[(size_t)fl * 64 + lane + 32];
                }
                sAt[lane * SAT_LD + p]        = a0;
                sAt[(lane + 32) * SAT_LD + p] = a1;
            }
        }
        __syncthreads();

        // ---- mainloop: 64 k-steps, rank-1 updates with packed f32x2
        #pragma unroll 4
        for (int k = 0; k < 64; k++) {
            const float* arow = sAt + k * SAT_LD + ty * 8;
            uint64_t a0 = *(const uint64_t*)(arow + 0);
            uint64_t a1 = *(const uint64_t*)(arow + 2);
            uint64_t a2 = *(const uint64_t*)(arow + 4);
            uint64_t a3 = *(const uint64_t*)(arow + 6);

            const ulonglong2* brow = (const ulonglong2*)(sWd + k * 128 + cx * 16);
            ulonglong2 b01 = brow[0];
            ulonglong2 b23 = brow[1];
            ulonglong2 b45 = brow[2];
            ulonglong2 b67 = brow[3];
            uint64_t b[8] = {b01.x, b01.y, b23.x, b23.y, b45.x, b45.y, b67.x, b67.y};

            #pragma unroll
            for (int c = 0; c < 8; c++) {
                fma2(acc[0][c], a0, b[c]);
                fma2(acc[1][c], a1, b[c]);
                fma2(acc[2][c], a2, b[c]);
                fma2(acc[3][c], a3, b[c]);
            }
        }
    }

    // ---- epilogue: relu + scatter atomicMax (out pre-zeroed, values >= 0)
    #pragma unroll
    for (int rp = 0; rp < 4; rp++) {
        #pragma unroll
        for (int half = 0; half < 2; half++) {
            int p  = ty * 8 + rp * 2 + half;
            int gp = p0 + p;
            if (gp >= N_PTS) continue;
            int fl = g_flat[gp];
            int* o = (int*)(out + (size_t)fl * 64 + cx * 8);
            #pragma unroll
            for (int c = 0; c < 8; c++) {
                uint32_t bits = half ? (uint32_t)(acc[rp][c] >> 32)
                                     : (uint32_t)(acc[rp][c] & 0xffffffffu);
                float v = __uint_as_float(bits);
                if (v > 0.f) atomicMax(o + c, __float_as_int(v));
            }
        }
    }
}

// ---------------------------------------------------------------------------
extern "C" void kernel_launch(void* const* d_in, const int* in_sizes, int n_in,
                              void* d_out, int out_size) {
    const float* points = (const float*)d_in[0];  // [400000, 5]
    const float* W1     = (const float*)d_in[1];  // [11, 64]
    const float* W2     = (const float*)d_in[2];  // [128, 64]
    float* out = (float*)d_out;                   // [219024, 64]

    cudaFuncSetAttribute(k_pf2, cudaFuncAttributeMaxDynamicSharedMemorySize,
                         SMEM_BYTES);

    k_init<<<4096, 256>>>(out);
    k_scatter<<<(N_PTS + 255) / 256, 256>>>(points);
    k_pf1<<<N_PTS / 8, 256>>>(points, W1);
    k_pf2<<<(N_PTS + BP - 1) / BP, 256, SMEM_BYTES>>>(points, W1, W2, out);
}

// round 3
// speedup vs baseline: 1.5452x; 1.5452x over previous
#include <cuda_runtime.h>
#include <cstdint>

#define N_PTS   400000
#define NXY     468
#define CANVAS  (468 * 468)          // 219024
#define VXY     0.32f
#define VZf     6.0f
#define PCMINX  (-74.88f)
#define PCMINY  (-74.88f)
#define PCMINZ  (-2.0f)

// -------- scratch (static device globals; no allocations allowed) ----------
__device__ int   g_flat[N_PTS];
__device__ int   g_cnt[CANVAS];
__device__ float g_vsum[CANVAS * 3];
__device__ float g_v1[CANVAS * 64];     // 56 MB
__device__ float g_pf1[N_PTS * 64];     // 102 MB

// packed f32x2 FMA (Blackwell FFMA2) — d = a*b + d, lanewise on 2 packed fp32
__device__ __forceinline__ void fma2(uint64_t& d, uint64_t a, uint64_t b) {
    asm("fma.rn.f32x2 %0, %1, %2, %0;" : "+l"(d) : "l"(a), "l"(b));
}

// ---------------------------------------------------------------------------
// K0: zero cnt / vsum / v1 / out
// ---------------------------------------------------------------------------
__global__ void k_init(float* __restrict__ out) {
    int idx = blockIdx.x * blockDim.x + threadIdx.x;
    int stride = gridDim.x * blockDim.x;
    const int n4 = (CANVAS * 64) / 4;
    float4 z = make_float4(0.f, 0.f, 0.f, 0.f);
    float4* o4 = (float4*)out;
    float4* v4 = (float4*)g_v1;
    for (int i = idx; i < n4; i += stride) {
        o4[i] = z;
        v4[i] = z;
    }
    for (int i = idx; i < CANVAS; i += stride) {
        g_cnt[i] = 0;
        g_vsum[3 * i + 0] = 0.f;
        g_vsum[3 * i + 1] = 0.f;
        g_vsum[3 * i + 2] = 0.f;
    }
}

// ---------------------------------------------------------------------------
// K1: per-point voxel index + count / xyz-sum scatter
// ---------------------------------------------------------------------------
__device__ __forceinline__ int voxel_coord(float v, float vmin, float vox, int nmax) {
    int c = (int)floorf(__fdiv_rn(v - vmin, vox));
    return min(max(c, 0), nmax - 1);
}

__global__ void k_scatter(const float* __restrict__ pts) {
    int i = blockIdx.x * blockDim.x + threadIdx.x;
    if (i >= N_PTS) return;
    float x = pts[i * 5 + 0];
    float y = pts[i * 5 + 1];
    float z = pts[i * 5 + 2];
    int cx = voxel_coord(x, PCMINX, VXY, NXY);
    int cy = voxel_coord(y, PCMINY, VXY, NXY);
    int flat = cy * NXY + cx;         // NZ==1 -> cz always 0
    g_flat[i] = flat;
    atomicAdd(&g_cnt[flat], 1);
    atomicAdd(&g_vsum[3 * flat + 0], x);
    atomicAdd(&g_vsum[3 * flat + 1], y);
    atomicAdd(&g_vsum[3 * flat + 2], z);
}

// ---------------------------------------------------------------------------
// K2: pf1 = relu(features @ W1); store to g_pf1, atomicMax into v1.
// warp per point; lane -> channels (lane, lane+32)
// ---------------------------------------------------------------------------
__global__ void k_pf1(const float* __restrict__ pts, const float* __restrict__ W1) {
    __shared__ float sW1[11 * 64];
    int tid = threadIdx.x;
    for (int i = tid; i < 11 * 64; i += 256) sW1[i] = W1[i];
    __syncthreads();

    int warp = tid >> 5;
    int lane = tid & 31;
    int i = blockIdx.x * 8 + warp;
    if (i >= N_PTS) return;

    float x  = pts[i * 5 + 0];
    float y  = pts[i * 5 + 1];
    float z  = pts[i * 5 + 2];
    float p3 = pts[i * 5 + 3];
    float p4 = pts[i * 5 + 4];

    int flat = g_flat[i];
    float inv = 1.0f / fmaxf((float)g_cnt[flat], 1.0f);
    float mx = g_vsum[3 * flat + 0] * inv;
    float my = g_vsum[3 * flat + 1] * inv;
    float mz = g_vsum[3 * flat + 2] * inv;

    int cxv = flat % NXY;
    int cyv = flat / NXY;

    float f[11];
    f[0] = x;  f[1] = y;  f[2] = z;  f[3] = p3;  f[4] = p4;
    f[5] = x - mx;  f[6] = y - my;  f[7] = z - mz;
    f[8]  = x - ((float)cxv * VXY + (VXY * 0.5f + PCMINX));
    f[9]  = y - ((float)cyv * VXY + (VXY * 0.5f + PCMINY));
    f[10] = z - (VZf * 0.5f + PCMINZ);

    float a0 = 0.f, a1 = 0.f;
    #pragma unroll
    for (int k = 0; k < 11; k++) {
        a0 = fmaf(f[k], sW1[k * 64 + lane], a0);
        a1 = fmaf(f[k], sW1[k * 64 + lane + 32], a1);
    }
    a0 = fmaxf(a0, 0.f);
    a1 = fmaxf(a1, 0.f);

    g_pf1[(size_t)i * 64 + lane]      = a0;
    g_pf1[(size_t)i * 64 + lane + 32] = a1;

    // relu >= 0 and v1 zero-initialized -> int atomicMax reproduces
    // where(occ, segment_max, 0) exactly.
    if (a0 > 0.f) atomicMax((int*)&g_v1[(size_t)flat * 64 + lane],      __float_as_int(a0));
    if (a1 > 0.f) atomicMax((int*)&g_v1[(size_t)flat * 64 + lane + 32], __float_as_int(a1));
}

// ---------------------------------------------------------------------------
// K3: pf2 = relu([pf1, v1[flat]] @ W2), scatter-max into out.
// 128 points x 64 outputs per block, 256 threads, 8x4 micro-tile as
// 4 row-pairs x 4 cols with packed f32x2 FMAs.
// A staged k-major in shared (conflict-free transpose); W2 duplicated {w,w}.
// ---------------------------------------------------------------------------
#define BP    128
#define PADA  132                       // k-row stride (words), mult of 4
#define SAT_WORDS (64 * PADA)           // 8448
#define SWD_WORDS (64 * 128)            // 8192
#define SMEM_BYTES ((SAT_WORDS + SWD_WORDS) * 4)   // 66560

__global__ __launch_bounds__(256, 3)
void k_pf2(const float* __restrict__ W2, float* __restrict__ out) {
    extern __shared__ float smem[];
    float* sAt = smem;                  // [64][PADA]  k-major A tile
    float* sWd = smem + SAT_WORDS;      // [64][128]   duplicated W2 chunk

    int tid = threadIdx.x;
    int p0  = blockIdx.x * BP;          // 3125 blocks * 128 = 400000 exactly
    int ty  = tid >> 4;                 // 0..15 : rows ty*8 .. ty*8+7
    int cxg = tid & 15;                 // 0..15 : cols cxg*4 .. cxg*4+3

    uint64_t acc[4][4];
    #pragma unroll
    for (int p = 0; p < 4; p++)
        #pragma unroll
        for (int c = 0; c < 4; c++) acc[p][c] = 0ull;

    const float4* pf1_4 = (const float4*)g_pf1;
    const float4* v1_4  = (const float4*)g_v1;

    #pragma unroll 1
    for (int chunk = 0; chunk < 2; chunk++) {
        if (chunk) __syncthreads();     // protect prev mainloop reads

        // ---- stage duplicated W2 chunk: sWd[k][2c..2c+1] = W2[ck*64+k][c]
        for (int i = tid; i < 4096; i += 256) {
            int k = i >> 6, c = i & 63;
            float wv = W2[(chunk * 64 + k) * 64 + c];
            *(float2*)&sWd[k * 128 + 2 * c] = make_float2(wv, wv);
        }

        // ---- stage A tile k-major.
        // i bits: [0:4)=pt_low, [4:8)=kq, [8:11)=pt_high  (2048 float4 total)
        // STS banks (16*kq + 4j + pt) mod 32 -> conflict-free.
        for (int i = tid; i < 2048; i += 256) {
            int pt = (i & 15) | ((i >> 8) << 4);   // 0..127
            int kq = (i >> 4) & 15;                // float4 index along k
            float4 v;
            if (chunk == 0) {
                v = pf1_4[(size_t)(p0 + pt) * 16 + kq];
            } else {
                int fl = g_flat[p0 + pt];
                v = v1_4[(size_t)fl * 16 + kq];
            }
            int kb = kq * 4;
            sAt[(kb + 0) * PADA + pt] = v.x;
            sAt[(kb + 1) * PADA + pt] = v.y;
            sAt[(kb + 2) * PADA + pt] = v.z;
            sAt[(kb + 3) * PADA + pt] = v.w;
        }
        __syncthreads();

        // ---- mainloop: 64 rank-1 updates, packed f32x2
        #pragma unroll 4
        for (int k = 0; k < 64; k++) {
            const float* arow = sAt + k * PADA + ty * 8;
            ulonglong2 ua0 = *(const ulonglong2*)(arow + 0);  // row pairs 01,23
            ulonglong2 ua1 = *(const ulonglong2*)(arow + 4);  // row pairs 45,67
            const float* brow = sWd + k * 128 + cxg * 8;
            ulonglong2 ub0 = *(const ulonglong2*)(brow + 0);  // cols c0,c1 dup
            ulonglong2 ub1 = *(const ulonglong2*)(brow + 4);  // cols c2,c3 dup

            fma2(acc[0][0], ua0.x, ub0.x); fma2(acc[0][1], ua0.x, ub0.y);
            fma2(acc[0][2], ua0.x, ub1.x); fma2(acc[0][3], ua0.x, ub1.y);
            fma2(acc[1][0], ua0.y, ub0.x); fma2(acc[1][1], ua0.y, ub0.y);
            fma2(acc[1][2], ua0.y, ub1.x); fma2(acc[1][3], ua0.y, ub1.y);
            fma2(acc[2][0], ua1.x, ub0.x); fma2(acc[2][1], ua1.x, ub0.y);
            fma2(acc[2][2], ua1.x, ub1.x); fma2(acc[2][3], ua1.x, ub1.y);
            fma2(acc[3][0], ua1.y, ub0.x); fma2(acc[3][1], ua1.y, ub0.y);
            fma2(acc[3][2], ua1.y, ub1.x); fma2(acc[3][3], ua1.y, ub1.y);
        }
    }

    // ---- epilogue: relu + scatter atomicMax (out pre-zeroed, values >= 0)
    #pragma unroll
    for (int p = 0; p < 4; p++) {
        #pragma unroll
        for (int half = 0; half < 2; half++) {
            int gp = p0 + ty * 8 + p * 2 + half;
            int fl = g_flat[gp];
            int* o = (int*)(out + (size_t)fl * 64 + cxg * 4);
            #pragma unroll
            for (int c = 0; c < 4; c++) {
                uint32_t bits = half ? (uint32_t)(acc[p][c] >> 32)
                                     : (uint32_t)(acc[p][c] & 0xffffffffu);
                float v = __uint_as_float(bits);
                if (v > 0.f) atomicMax(o + c, __float_as_int(v));
            }
        }
    }
}

// ---------------------------------------------------------------------------
extern "C" void kernel_launch(void* const* d_in, const int* in_sizes, int n_in,
                              void* d_out, int out_size) {
    const float* points = (const float*)d_in[0];  // [400000, 5]
    const float* W1     = (const float*)d_in[1];  // [11, 64]
    const float* W2     = (const float*)d_in[2];  // [128, 64]
    float* out = (float*)d_out;                   // [219024, 64]

    cudaFuncSetAttribute(k_pf2, cudaFuncAttributeMaxDynamicSharedMemorySize,
                         SMEM_BYTES);

    k_init<<<8192, 256>>>(out);
    k_scatter<<<(N_PTS + 255) / 256, 256>>>(points);
    k_pf1<<<N_PTS / 8, 256>>>(points, W1);
    k_pf2<<<N_PTS / BP, 256, SMEM_BYTES>>>(W2, out);
}

// round 6
// speedup vs baseline: 1.7560x; 1.1364x over previous
#include <cuda_runtime.h>
#include <cstdint>

#define N_PTS   400000
#define NTILE   1563                 // ceil(400000 / 256)
#define NPAD    (NTILE * 256)        // 400128
#define NXY     468
#define CANVAS  (468 * 468)          // 219024
#define VXY     0.32f
#define VZf     6.0f
#define PCMINX  (-74.88f)
#define PCMINY  (-74.88f)
#define PCMINZ  (-2.0f)

// -------- scratch (static device globals; no allocations allowed) ----------
__device__ int   g_flat[NPAD];                 // padded; tail zeroed
__device__ int   g_cnt[CANVAS];
__device__ float g_vsum[CANVAS * 3];
__device__ float g_v1[CANVAS * 64];            // 56 MB
__device__ float g_pf1[(size_t)NTILE * 64 * 256];  // tile-major [tile][k][pt]

// packed f32x2 FMA (Blackwell FFMA2) — d = a*b + d on 2 packed fp32
__device__ __forceinline__ void fma2(uint64_t& d, uint64_t a, uint64_t b) {
    asm("fma.rn.f32x2 %0, %1, %2, %0;" : "+l"(d) : "l"(a), "l"(b));
}

// ---------------------------------------------------------------------------
// K0: zero cnt / vsum / v1 / out / g_flat tail
// ---------------------------------------------------------------------------
__global__ void k_init(float* __restrict__ out) {
    int idx = blockIdx.x * blockDim.x + threadIdx.x;
    int stride = gridDim.x * blockDim.x;
    const int n4 = (CANVAS * 64) / 4;
    float4 z = make_float4(0.f, 0.f, 0.f, 0.f);
    float4* o4 = (float4*)out;
    float4* v4 = (float4*)g_v1;
    for (int i = idx; i < n4; i += stride) {
        o4[i] = z;
        v4[i] = z;
    }
    for (int i = idx; i < CANVAS; i += stride) {
        g_cnt[i] = 0;
        g_vsum[3 * i + 0] = 0.f;
        g_vsum[3 * i + 1] = 0.f;
        g_vsum[3 * i + 2] = 0.f;
    }
    for (int i = N_PTS + idx; i < NPAD; i += stride) g_flat[i] = 0;
}

// ---------------------------------------------------------------------------
// K1: per-point voxel index + count / xyz-sum scatter
// ---------------------------------------------------------------------------
__device__ __forceinline__ int voxel_coord(float v, float vmin, float vox, int nmax) {
    int c = (int)floorf(__fdiv_rn(v - vmin, vox));
    return min(max(c, 0), nmax - 1);
}

__global__ void k_scatter(const float* __restrict__ pts) {
    int i = blockIdx.x * blockDim.x + threadIdx.x;
    if (i >= N_PTS) return;
    float x = pts[i * 5 + 0];
    float y = pts[i * 5 + 1];
    float z = pts[i * 5 + 2];
    int cx = voxel_coord(x, PCMINX, VXY, NXY);
    int cy = voxel_coord(y, PCMINY, VXY, NXY);
    int flat = cy * NXY + cx;          // NZ==1 -> cz always 0
    g_flat[i] = flat;
    atomicAdd(&g_cnt[flat], 1);
    atomicAdd(&g_vsum[3 * flat + 0], x);
    atomicAdd(&g_vsum[3 * flat + 1], y);
    atomicAdd(&g_vsum[3 * flat + 2], z);
}

// ---------------------------------------------------------------------------
// K2: thread-per-point pf1 = relu(features @ W1).
// - atomicMax into v1 (values >= 0, v1 zero-init -> int max == float max,
//   and reproduces where(occ, segment_max, 0) exactly)
// - outputs transposed in smem, then written COALESCED to g_pf1 in the
//   tile-major layout [tile][k(64)][pt(256)] that k_pf2 consumes directly.
// ---------------------------------------------------------------------------
__global__ __launch_bounds__(256) void k_pf1(const float* __restrict__ pts,
                                             const float* __restrict__ W1) {
    __shared__ float sW1[11 * 64];
    __shared__ float sT[64 * 256];     // [k][pt] transposed outputs
    int tid = threadIdx.x;
    for (int i = tid; i < 11 * 64; i += 256) sW1[i] = W1[i];
    __syncthreads();

    int gp = blockIdx.x * 256 + tid;
    bool valid = (gp < N_PTS);

    float f[11];
    #pragma unroll
    for (int k = 0; k < 11; k++) f[k] = 0.f;
    int flat = 0;

    if (valid) {
        float x  = pts[gp * 5 + 0];
        float y  = pts[gp * 5 + 1];
        float z  = pts[gp * 5 + 2];
        float p3 = pts[gp * 5 + 3];
        float p4 = pts[gp * 5 + 4];
        flat = g_flat[gp];
        float inv = 1.0f / fmaxf((float)g_cnt[flat], 1.0f);
        float mx = g_vsum[3 * flat + 0] * inv;
        float my = g_vsum[3 * flat + 1] * inv;
        float mz = g_vsum[3 * flat + 2] * inv;
        int cxv = flat % NXY;
        int cyv = flat / NXY;
        f[0] = x;  f[1] = y;  f[2] = z;  f[3] = p3;  f[4] = p4;
        f[5] = x - mx;  f[6] = y - my;  f[7] = z - mz;
        f[8]  = x - ((float)cxv * VXY + (VXY * 0.5f + PCMINX));
        f[9]  = y - ((float)cyv * VXY + (VXY * 0.5f + PCMINY));
        f[10] = z - (VZf * 0.5f + PCMINZ);
    }

    const float4* w4 = (const float4*)sW1;   // [11][16] float4
    #pragma unroll 4
    for (int cg = 0; cg < 16; cg++) {        // 4 output channels per group
        float a0 = 0.f, a1 = 0.f, a2 = 0.f, a3 = 0.f;
        #pragma unroll
        for (int k = 0; k < 11; k++) {
            float4 w = w4[k * 16 + cg];      // warp-uniform broadcast
            a0 = fmaf(f[k], w.x, a0);
            a1 = fmaf(f[k], w.y, a1);
            a2 = fmaf(f[k], w.z, a2);
            a3 = fmaf(f[k], w.w, a3);
        }
        a0 = fmaxf(a0, 0.f); a1 = fmaxf(a1, 0.f);
        a2 = fmaxf(a2, 0.f); a3 = fmaxf(a3, 0.f);
        int c = cg * 4;
        sT[(c + 0) * 256 + tid] = a0;        // bank = tid%32: conflict-free
        sT[(c + 1) * 256 + tid] = a1;
        sT[(c + 2) * 256 + tid] = a2;
        sT[(c + 3) * 256 + tid] = a3;
        if (valid) {
            int* vb = (int*)&g_v1[(size_t)flat * 64 + c];
            if (a0 > 0.f) atomicMax(vb + 0, __float_as_int(a0));
            if (a1 > 0.f) atomicMax(vb + 1, __float_as_int(a1));
            if (a2 > 0.f) atomicMax(vb + 2, __float_as_int(a2));
            if (a3 > 0.f) atomicMax(vb + 3, __float_as_int(a3));
        }
    }
    __syncthreads();

    // coalesced tile write: [k][pt] float4s
    float4* dst = (float4*)(g_pf1 + (size_t)blockIdx.x * 64 * 256);
    const float4* src = (const float4*)sT;
    #pragma unroll 4
    for (int i = tid; i < 64 * 64; i += 256) dst[i] = src[i];
}

// ---------------------------------------------------------------------------
// K3: pf2 = relu([pf1, v1[flat]] @ W2), scatter-max into out.
// Tile: 256 points x 64 cols per block, 256 threads.
// Thread (ty=tid>>3, cx=tid&7): 8 points (4 pairs) x 8 cols, 32 u64 f32x2 accs.
// Per k-step per thread: 2 LDS.128 (A, conflict-free) + 4 LDS.128 (B dup,
// interleaved [k][j][cx] layout -> dense 128B lines, conflict-free) + 32 fma2.
// ---------------------------------------------------------------------------
#define SA_S    260                        // A row stride (words): 4-bank shift
#define SA_WORDS (64 * SA_S)               // 16640
#define SB_WORDS (64 * 128)                // 8192  (dup'd, interleaved)
#define SMEM_BYTES ((SA_WORDS + SB_WORDS) * 4)   // 99328

__global__ __launch_bounds__(256, 2)
void k_pf2(const float* __restrict__ W2, float* __restrict__ out) {
    extern __shared__ float smem[];
    float* sA = smem;                      // [64][SA_S] k-major A tile
    float* sB = smem + SA_WORDS;           // [64][4j][8cx][2col x dup]

    int tid = threadIdx.x;
    int p0  = blockIdx.x * 256;
    int ty  = tid >> 3;                    // 0..31 -> points ty*8 .. +7
    int cx  = tid & 7;                     // 0..7  -> cols  cx*8 .. +7

    uint64_t acc[4][8];
    #pragma unroll
    for (int p = 0; p < 4; p++)
        #pragma unroll
        for (int c = 0; c < 8; c++) acc[p][c] = 0ull;

    #pragma unroll 1
    for (int chunk = 0; chunk < 2; chunk++) {
        if (chunk) __syncthreads();

        // ---- stage B chunk, duplicated + interleaved:
        // col c -> word off = k*128 + ((c&7)>>1)*32 + (c>>3)*4 + (c&1)*2
        for (int i = tid; i < 4096; i += 256) {
            int k = i >> 6, c = i & 63;
            float wv = W2[(chunk * 64 + k) * 64 + c];
            int off = k * 128 + (((c & 7) >> 1) << 5) + ((c >> 3) << 2)
                    + ((c & 1) << 1);
            *(float2*)&sB[off] = make_float2(wv, wv);
        }

        // ---- stage A tile k-major [64][SA_S]
        if (chunk == 0) {
            // pure coalesced copy from tile-major g_pf1
            const float4* src = (const float4*)(g_pf1 + (size_t)blockIdx.x * 64 * 256);
            #pragma unroll 4
            for (int i = tid; i < 4096; i += 256) {
                int k = i >> 6, q = i & 63;
                *(float4*)&sA[k * SA_S + q * 4] = src[i];
            }
        } else {
            // gather v1 rows; bits: [0:4)=pt_lo [4:8)=q [8:12)=pt_hi
            for (int i = tid; i < 4096; i += 256) {
                int pt = (i & 15) | ((i >> 8) << 4);
                int q  = (i >> 4) & 15;
                int fl = g_flat[p0 + pt];          // padded -> always valid
                float4 v = ((const float4*)(g_v1 + (size_t)fl * 64))[q];
                int kb = q * 4;
                sA[(kb + 0) * SA_S + pt] = v.x;    // stride 260: q-groups on
                sA[(kb + 1) * SA_S + pt] = v.y;    // disjoint bank halves
                sA[(kb + 2) * SA_S + pt] = v.z;
                sA[(kb + 3) * SA_S + pt] = v.w;
            }
        }
        __syncthreads();

        // ---- mainloop: 64 rank-1 updates
        #pragma unroll 4
        for (int k = 0; k < 64; k++) {
            const float* a = sA + k * SA_S + ty * 8;
            ulonglong2 A01 = *(const ulonglong2*)(a + 0);   // pairs (0,1),(2,3)
            ulonglong2 A23 = *(const ulonglong2*)(a + 4);   // pairs (4,5),(6,7)
            const float* b = sB + k * 128 + cx * 4;
            ulonglong2 B0 = *(const ulonglong2*)(b + 0);    // cols 8cx+0,1 dup
            ulonglong2 B1 = *(const ulonglong2*)(b + 32);   // cols 8cx+2,3 dup
            ulonglong2 B2 = *(const ulonglong2*)(b + 64);   // cols 8cx+4,5 dup
            ulonglong2 B3 = *(const ulonglong2*)(b + 96);   // cols 8cx+6,7 dup

            uint64_t A[4] = {A01.x, A01.y, A23.x, A23.y};
            uint64_t B[8] = {B0.x, B0.y, B1.x, B1.y, B2.x, B2.y, B3.x, B3.y};
            #pragma unroll
            for (int p = 0; p < 4; p++) {
                fma2(acc[p][0], A[p], B[0]); fma2(acc[p][1], A[p], B[1]);
                fma2(acc[p][2], A[p], B[2]); fma2(acc[p][3], A[p], B[3]);
                fma2(acc[p][4], A[p], B[4]); fma2(acc[p][5], A[p], B[5]);
                fma2(acc[p][6], A[p], B[6]); fma2(acc[p][7], A[p], B[7]);
            }
        }
    }

    // ---- epilogue: relu + scatter atomicMax (out pre-zeroed, values >= 0)
    #pragma unroll
    for (int p = 0; p < 4; p++) {
        #pragma unroll
        for (int half = 0; half < 2; half++) {
            int gp = p0 + ty * 8 + p * 2 + half;
            if (gp >= N_PTS) continue;
            int fl = g_flat[gp];
            int* o = (int*)(out + (size_t)fl * 64 + cx * 8);
            #pragma unroll
            for (int c = 0; c < 8; c++) {
                uint32_t bits = half ? (uint32_t)(acc[p][c] >> 32)
                                     : (uint32_t)(acc[p][c] & 0xffffffffu);
                float v = __uint_as_float(bits);
                if (v > 0.f) atomicMax(o + c, __float_as_int(v));
            }
        }
    }
}

// ---------------------------------------------------------------------------
extern "C" void kernel_launch(void* const* d_in, const int* in_sizes, int n_in,
                              void* d_out, int out_size) {
    const float* points = (const float*)d_in[0];  // [400000, 5]
    const float* W1     = (const float*)d_in[1];  // [11, 64]
    const float* W2     = (const float*)d_in[2];  // [128, 64]
    float* out = (float*)d_out;                   // [219024, 64]

    cudaFuncSetAttribute(k_pf2, cudaFuncAttributeMaxDynamicSharedMemorySize,
                         SMEM_BYTES);

    k_init<<<8192, 256>>>(out);
    k_scatter<<<(N_PTS + 255) / 256, 256>>>(points);
    k_pf1<<<NTILE, 256>>>(points, W1);
    k_pf2<<<NTILE, 256, SMEM_BYTES>>>(W2, out);
}